// round 15
// baseline (speedup 1.0000x reference)
#include <cuda_runtime.h>
#include <cuda_fp16.h>
#include <math.h>

// ---------------- problem dims (fixed) ----------------
#define T_    2048
#define HID_  1024
#define H_    16
#define DK_   64
#define DV_   128
#define VAL_  2048
#define QKD_  1024
#define CONV_ 4
#define BIGN_ 6272   // q(1024)+k(1024)+v(2048)+g(2048)+ab_pad(128)

// fp16 weight buffer offsets (halves)
#define WQKVG_OFF 0u
#define WAB_OFF   6291456u              // 6144*1024
#define WO_OFF    6422528u              // + 128*1024
#define WOUT_OFF  8519680u              // + 1024*2048
#define WT_HALVES 9568256u              // + 1024*1024

// ---------------- scratch (device globals) ----------------
__device__ __half g_wt  [WT_HALVES];
__device__ __half g_xh  [T_*HID_];
__device__ float  g_rs  [T_];
__device__ float  g_big [T_*BIGN_];
__device__ float  g_q   [T_*QKD_];
__device__ float  g_k   [T_*QKD_];
__device__ float  g_v   [T_*VAL_];
__device__ float  g_beta[T_*H_];
__device__ float  g_eg  [T_*H_];
__device__ float  g_o   [T_*VAL_];
__device__ __half g_o2h [T_*VAL_];
__device__ __half g_y1h [T_*HID_];

// ---------------- helpers ----------------
__device__ __forceinline__ unsigned pack2(float a, float b) {
    __half2 h = __floats2half2_rn(a, b);
    return *reinterpret_cast<unsigned*>(&h);
}
#define MMA_F16(C, A, B)                                                      \
    asm volatile("mma.sync.aligned.m16n8k16.row.col.f32.f16.f16.f32 "         \
                 "{%0,%1,%2,%3}, {%4,%5,%6,%7}, {%8,%9}, {%0,%1,%2,%3};"      \
                 : "+f"((C)[0]), "+f"((C)[1]), "+f"((C)[2]), "+f"((C)[3])     \
                 : "r"((A)[0]), "r"((A)[1]), "r"((A)[2]), "r"((A)[3]),        \
                   "r"((B)[0]), "r"((B)[1]))
#define LDSM4(R0, R1, R2, R3, addr)                                           \
    asm volatile("ldmatrix.sync.aligned.m8n8.x4.shared.b16 {%0,%1,%2,%3}, [%4];" \
                 : "=r"(R0), "=r"(R1), "=r"(R2), "=r"(R3) : "r"(addr))
#define CP16(dst, src) \
    asm volatile("cp.async.cg.shared.global [%0], [%1], 16;\n" :: "r"(dst), "l"(src))

// ---------------- 0) ALL weights -> fp16 (single kernel) ----------------
__global__ void cvt_all_h(const float4* __restrict__ wq,
                          const float4* __restrict__ wk,
                          const float4* __restrict__ wv,
                          const float4* __restrict__ wg,
                          const float4* __restrict__ wo,
                          const float4* __restrict__ wout,
                          const float*  __restrict__ a_w,
                          const float*  __restrict__ b_w,
                          __half* __restrict__ dst) {
    int idx = blockIdx.x * 256 + threadIdx.x;       // 0 .. 1196031
    if (idx < 1179648) {
        int f4 = idx * 2;
        const float4* src; int off;
        if (f4 < 262144)       { src = wq;   off = f4; }
        else if (f4 < 524288)  { src = wk;   off = f4 - 262144; }
        else if (f4 < 1048576) { src = wv;   off = f4 - 524288; }
        else if (f4 < 1572864) { src = wg;   off = f4 - 1048576; }
        else if (f4 < 2097152) { src = wo;   off = f4 - 1572864; }
        else                   { src = wout; off = f4 - 2097152; }
        unsigned hbase = (unsigned)idx * 8;
        if (hbase >= WAB_OFF) hbase += 131072;      // skip ab region
        float4 v0 = src[off], v1 = src[off + 1];
        uint4 u;
        u.x = pack2(v0.x, v0.y); u.y = pack2(v0.z, v0.w);
        u.z = pack2(v1.x, v1.y); u.w = pack2(v1.z, v1.w);
        *(uint4*)&dst[hbase] = u;
    } else {
        int u2 = idx - 1179648;                     // 0..16383
        int base = u2 * 8;
        int row = base >> 10, col = base & 1023;
        float vals[8];
        #pragma unroll
        for (int i = 0; i < 8; i++) vals[i] = 0.f;
        if (row < 16) {
            #pragma unroll
            for (int i = 0; i < 8; i++) vals[i] = a_w[row * 1024 + col + i];
        } else if (row < 32) {
            #pragma unroll
            for (int i = 0; i < 8; i++) vals[i] = b_w[(row - 16) * 1024 + col + i];
        }
        uint4 uu;
        uu.x = pack2(vals[0], vals[1]); uu.y = pack2(vals[2], vals[3]);
        uu.z = pack2(vals[4], vals[5]); uu.w = pack2(vals[6], vals[7]);
        *(uint4*)&dst[WAB_OFF + base] = uu;
    }
}

// ---------------- 1a) RMSNorm reduce ----------------
__global__ void rms_reduce_kernel(const float* __restrict__ h,
                                  float* __restrict__ rs) {
    int row = blockIdx.x * 8 + (threadIdx.x >> 5);
    int lane = threadIdx.x & 31;
    const float4* p = (const float4*)(h + (size_t)row * HID_);
    float ss = 0.f;
    #pragma unroll
    for (int i = 0; i < 8; i++) {
        float4 v = p[lane + i * 32];
        ss += v.x * v.x + v.y * v.y + v.z * v.z + v.w * v.w;
    }
    for (int off = 16; off > 0; off >>= 1) ss += __shfl_xor_sync(0xffffffffu, ss, off);
    if (lane == 0) rs[row] = rsqrtf(ss / (float)HID_ + 1e-6f);
}

// ---------------- 1b) RMSNorm apply -> fp16 ----------------
__global__ void rms_apply_kernel(const float* __restrict__ h,
                                 const float* __restrict__ rs,
                                 const float* __restrict__ w,
                                 __half* __restrict__ xh) {
    int idx = blockIdx.x * blockDim.x + threadIdx.x;
    int t = idx >> 8;
    float s = rs[t];
    float4 hv = ((const float4*)h)[idx];
    float4 wv = ((const float4*)w)[idx & 255];
    uint2 u;
    u.x = pack2(hv.x * s * wv.x, hv.y * s * wv.y);
    u.y = pack2(hv.z * s * wv.z, hv.w * s * wv.w);
    ((uint2*)xh)[idx] = u;
}

// ---------------- 2) 128x128 FP16 GEMM, 3-stage cp.async + ldmatrix -------
// Fragment loads hoisted: A frags for both k16 steps + B(k16=0) load before
// the first MMA burst; B(k16=1) loads overlap the first burst.
#define HPAD 40
#define STAGEB 10240u                   // 128*40 halves * 2B
template<int OUT_HALF>
__global__ __launch_bounds__(256, 2) void gemm128_h(const __half* __restrict__ X,
                                                    const __half* __restrict__ W,
                                                    float* __restrict__ Cf,
                                                    __half* __restrict__ Ch,
                                                    int K, int ldc) {
    extern __shared__ __half smem[];    // [A0 A1 A2 B0 B1 B2], 10240B each
    const __half* Xt = X + (size_t)blockIdx.y * 128 * K;
    const __half* Wt = W + (size_t)blockIdx.x * 128 * K;
    int tid = threadIdx.x, wid = tid >> 5, lane = tid & 31;
    int wm = (wid >> 2) * 64, wn = (wid & 3) * 32;
    int gid = lane >> 2, tig = lane & 3;
    int t4 = lane >> 3, l8 = lane & 7;
    int aRow = (t4 & 1) * 8 + l8, aCol = (t4 >> 1) * 8;
    int bRow = (t4 >> 1) * 8 + l8, bCol = (t4 & 1) * 8;

    int lr = tid >> 1, hc = (tid & 1) * 16;
    const __half* xs = Xt + (size_t)lr * K + hc;
    const __half* ws = Wt + (size_t)lr * K + hc;
    unsigned abase = (unsigned)__cvta_generic_to_shared(smem);
    unsigned bbase = abase + 3 * STAGEB;
    unsigned woff = (unsigned)(lr * HPAD + hc) * 2;

    float acc[16][4];
    #pragma unroll
    for (int i = 0; i < 16; i++)
        #pragma unroll
        for (int j = 0; j < 4; j++) acc[i][j] = 0.f;

    // prologue: stages 0,1
    #pragma unroll
    for (int s = 0; s < 2; s++) {
        unsigned da = abase + s * STAGEB + woff;
        unsigned db = bbase + s * STAGEB + woff;
        int k0 = s * 32;
        CP16(da, xs + k0); CP16(da + 16, xs + k0 + 8);
        CP16(db, ws + k0); CP16(db + 16, ws + k0 + 8);
        asm volatile("cp.async.commit_group;\n");
    }

    int nk = K / 32;
    for (int it = 0; it < nk; it++) {
        asm volatile("cp.async.wait_group 1;\n");   // stage `it` ready
        __syncthreads();
        if (it + 2 < nk) {
            int s = (it + 2) % 3;
            int k0 = (it + 2) * 32;
            unsigned da = abase + s * STAGEB + woff;
            unsigned db = bbase + s * STAGEB + woff;
            CP16(da, xs + k0); CP16(da + 16, xs + k0 + 8);
            CP16(db, ws + k0); CP16(db + 16, ws + k0 + 8);
        }
        asm volatile("cp.async.commit_group;\n");
        unsigned ab = abase + (it % 3) * STAGEB;
        unsigned bb = bbase + (it % 3) * STAGEB;

        // hoisted fragment loads: A for both k16 steps, B for step 0
        unsigned a[2][4][4], b0[4][2], b1[4][2];
        #pragma unroll
        for (int k16 = 0; k16 < 2; k16++) {
            int kk = k16 * 16;
            #pragma unroll
            for (int mt = 0; mt < 4; mt++) {
                unsigned addr = ab + ((wm + mt * 16 + aRow) * HPAD + kk + aCol) * 2;
                LDSM4(a[k16][mt][0], a[k16][mt][1], a[k16][mt][2], a[k16][mt][3], addr);
            }
        }
        #pragma unroll
        for (int p = 0; p < 2; p++) {
            unsigned addr = bb + ((wn + p * 16 + bRow) * HPAD + 0 + bCol) * 2;
            LDSM4(b0[p*2][0], b0[p*2][1], b0[p*2+1][0], b0[p*2+1][1], addr);
        }
        // B frags for step 1 (independent of step-0 MMAs -> overlaps them)
        #pragma unroll
        for (int p = 0; p < 2; p++) {
            unsigned addr = bb + ((wn + p * 16 + bRow) * HPAD + 16 + bCol) * 2;
            LDSM4(b1[p*2][0], b1[p*2][1], b1[p*2+1][0], b1[p*2+1][1], addr);
        }
        #pragma unroll
        for (int mt = 0; mt < 4; mt++)
            #pragma unroll
            for (int nt = 0; nt < 4; nt++)
                MMA_F16(acc[mt * 4 + nt], a[0][mt], b0[nt]);
        #pragma unroll
        for (int mt = 0; mt < 4; mt++)
            #pragma unroll
            for (int nt = 0; nt < 4; nt++)
                MMA_F16(acc[mt * 4 + nt], a[1][mt], b1[nt]);
    }

    size_t base = (size_t)blockIdx.y * 128 * ldc + blockIdx.x * 128;
    #pragma unroll
    for (int mt = 0; mt < 4; mt++) {
        int row = wm + mt * 16 + gid;
        #pragma unroll
        for (int nt = 0; nt < 4; nt++) {
            int col = wn + nt * 8 + tig * 2;
            float* c = acc[mt * 4 + nt];
            if (OUT_HALF) {
                *(unsigned*)&Ch[base + (size_t)row * ldc + col]       = pack2(c[0], c[1]);
                *(unsigned*)&Ch[base + (size_t)(row + 8) * ldc + col] = pack2(c[2], c[3]);
            } else {
                *(float2*)&Cf[base + (size_t)row * ldc + col]       = make_float2(c[0], c[1]);
                *(float2*)&Cf[base + (size_t)(row + 8) * ldc + col] = make_float2(c[2], c[3]);
            }
        }
    }
}

// ---------------- 3a) conv(q,k) + silu + DC-removal + L2 norm + beta/eg ---
__global__ void conv_qk_kernel(const float* __restrict__ big,
                               const float* __restrict__ wq,
                               const float* __restrict__ wk,
                               const float* __restrict__ dt_bias,
                               const float* __restrict__ A_log,
                               float* __restrict__ qout,
                               float* __restrict__ kout,
                               float* __restrict__ beta,
                               float* __restrict__ eg) {
    int gw = (blockIdx.x * blockDim.x + threadIdx.x) >> 5;  // t*H + h
    int lane = threadIdx.x & 31;
    int t = gw >> 4, h = gw & 15;
    float da = 0.f, db = 0.f;
    if (lane == 0) {
        da = big[(size_t)t * BIGN_ + 6144 + h];
        db = big[(size_t)t * BIGN_ + 6160 + h];
    }
    int c0 = h * 64 + lane * 2;
    float4 wq0 = ((const float4*)wq)[c0], wq1 = ((const float4*)wq)[c0 + 1];
    float4 wk0 = ((const float4*)wk)[c0], wk1 = ((const float4*)wk)[c0 + 1];
    float q0 = 0.f, q1 = 0.f, k0 = 0.f, k1 = 0.f;
    #pragma unroll
    for (int i = 0; i < CONV_; i++) {
        int tt = t - 3 + i;
        if (tt >= 0) {
            const float* row = big + (size_t)tt * BIGN_;
            float2 xq = *(const float2*)(row + c0);
            float2 xk = *(const float2*)(row + 1024 + c0);
            q0 = fmaf(xq.x, (&wq0.x)[i], q0);
            q1 = fmaf(xq.y, (&wq1.x)[i], q1);
            k0 = fmaf(xk.x, (&wk0.x)[i], k0);
            k1 = fmaf(xk.y, (&wk1.x)[i], k1);
        }
    }
    q0 *= 1.f / (1.f + __expf(-q0));
    q1 *= 1.f / (1.f + __expf(-q1));
    k0 *= 1.f / (1.f + __expf(-k0));
    k1 *= 1.f / (1.f + __expf(-k1));
    float s = k0 + k1;
    for (int off = 16; off > 0; off >>= 1) s += __shfl_xor_sync(0xffffffffu, s, off);
    float mean = s * (1.f / 64.f);
    k0 -= mean; k1 -= mean;
    float ss = k0 * k0 + k1 * k1;
    for (int off = 16; off > 0; off >>= 1) ss += __shfl_xor_sync(0xffffffffu, ss, off);
    float sc = rsqrtf(ss + 1e-6f);
    float qq = q0 * q0 + q1 * q1;
    for (int off = 16; off > 0; off >>= 1) qq += __shfl_xor_sync(0xffffffffu, qq, off);
    float qs = rsqrtf(qq + 1e-6f) * 0.125f;
    *(float2*)&qout[(size_t)gw * DK_ + lane * 2] = make_float2(q0 * qs, q1 * qs);
    *(float2*)&kout[(size_t)gw * DK_ + lane * 2] = make_float2(k0 * sc, k1 * sc);
    if (lane == 0) {
        beta[gw] = 1.f / (1.f + expf(-db));
        float z = da + dt_bias[h];
        float sp = (z > 20.f) ? z : log1pf(expf(z));
        eg[gw] = expf(-expf(A_log[h]) * sp);
    }
}

// ---------------- 3b) conv(v) + silu ----------------
__global__ void conv_v_kernel(const float* __restrict__ big,
                              const float* __restrict__ wv,
                              float* __restrict__ ov) {
    int idx = blockIdx.x * 256 + threadIdx.x;   // over T_*2048/4
    int t = idx >> 9;
    int c4 = (idx & 511) * 4;
    float4 w0 = ((const float4*)wv)[c4 + 0];
    float4 w1 = ((const float4*)wv)[c4 + 1];
    float4 w2 = ((const float4*)wv)[c4 + 2];
    float4 w3 = ((const float4*)wv)[c4 + 3];
    float4 acc = make_float4(0.f, 0.f, 0.f, 0.f);
    #pragma unroll
    for (int i = 0; i < CONV_; i++) {
        int tt = t - 3 + i;
        if (tt >= 0) {
            float4 xv = *(const float4*)(big + (size_t)tt * BIGN_ + 2048 + c4);
            acc.x = fmaf(xv.x, (&w0.x)[i], acc.x);
            acc.y = fmaf(xv.y, (&w1.x)[i], acc.y);
            acc.z = fmaf(xv.z, (&w2.x)[i], acc.z);
            acc.w = fmaf(xv.w, (&w3.x)[i], acc.w);
        }
    }
    acc.x *= 1.f / (1.f + __expf(-acc.x));
    acc.y *= 1.f / (1.f + __expf(-acc.y));
    acc.z *= 1.f / (1.f + __expf(-acc.z));
    acc.w *= 1.f / (1.f + __expf(-acc.w));
    *(float4*)&ov[(size_t)t * VAL_ + c4] = acc;
}

// ---------------- 4) gated delta-rule scan (dv split 8) ----------------
__global__ __launch_bounds__(128) void scan_kernel(const float* __restrict__ q,
                                                   const float* __restrict__ k,
                                                   const float* __restrict__ v,
                                                   const float* __restrict__ beta,
                                                   const float* __restrict__ eg,
                                                   float* __restrict__ o) {
    int h = blockIdx.x >> 3;
    int dvq = blockIdx.x & 7;
    int tid = threadIdx.x;
    int dv_l = tid >> 3, qr = tid & 7;
    int dv = dvq * 16 + dv_l;

    __shared__ float ks[4][4][64], qs[4][4][64], vs[4][4][16], gb[4][4][2];

    int role = tid >> 5;
    int lane = tid & 31;

    float S[8];
    #pragma unroll
    for (int i = 0; i < 8; i++) S[i] = 0.f;

    const int NP = T_ / 4;   // 512 stages

    #define ISSUE_STAGE(P) do {                                                       \
        int set_ = (P) & 3;                                                           \
        int t0_ = (P) * 4;                                                            \
        if (role == 0) {                                                              \
            _Pragma("unroll")                                                         \
            for (int r2 = 0; r2 < 2; r2++) {                                          \
                int idx = lane + r2 * 32;                                             \
                int ss = idx >> 4, ch = idx & 15;                                     \
                unsigned d = (unsigned)__cvta_generic_to_shared(&ks[set_][ss][ch*4]); \
                const float* sp = k + ((size_t)(t0_ + ss) * H_ + h) * DK_ + ch*4;     \
                CP16(d, sp);                                                          \
            }                                                                         \
        } else if (role == 1) {                                                       \
            _Pragma("unroll")                                                         \
            for (int r2 = 0; r2 < 2; r2++) {                                          \
                int idx = lane + r2 * 32;                                             \
                int ss = idx >> 4, ch = idx & 15;                                     \
                unsigned d = (unsigned)__cvta_generic_to_shared(&qs[set_][ss][ch*4]); \
                const float* sp = q + ((size_t)(t0_ + ss) * H_ + h) * DK_ + ch*4;     \
                CP16(d, sp);                                                          \
            }                                                                         \
        } else if (role == 2) {                                                       \
            if (lane < 16) {                                                          \
                int ss = lane >> 2, ch = lane & 3;                                    \
                unsigned d = (unsigned)__cvta_generic_to_shared(&vs[set_][ss][ch*4]); \
                const float* sp = v + ((size_t)(t0_ + ss) * H_ + h) * DV_ + dvq*16 + ch*4; \
                CP16(d, sp);                                                          \
            }                                                                         \
        } else if (lane < 8) {                                                        \
            int ss = lane >> 1; int which = lane & 1;                                 \
            unsigned d = (unsigned)__cvta_generic_to_shared(&gb[set_][ss][which]);    \
            const float* sp = (which ? beta : eg) + (size_t)(t0_ + ss) * H_ + h;      \
            asm volatile("cp.async.ca.shared.global [%0], [%1], 4;\n" :: "r"(d), "l"(sp)); \
        }                                                                             \
    } while (0)

    #pragma unroll
    for (int p = 0; p < 3; p++) {
        ISSUE_STAGE(p);
        asm volatile("cp.async.commit_group;\n");
    }

    for (int p = 0; p < NP; p++) {
        asm volatile("cp.async.wait_group 2;\n");
        __syncthreads();
        if (p + 3 < NP) ISSUE_STAGE(p + 3);
        asm volatile("cp.async.commit_group;\n");
        int set = p & 3;
        #pragma unroll
        for (int s = 0; s < 4; s++) {
            float egv = gb[set][s][0];
            float bt  = gb[set][s][1];
            float vv  = vs[set][s][dv_l];
            float kr[8];
            *(float4*)&kr[0] = *(const float4*)&ks[set][s][qr*8];
            *(float4*)&kr[4] = *(const float4*)&ks[set][s][qr*8 + 4];
            float kv0, kv1, kv2, kv3;
            S[0] *= egv; kv0 = kr[0] * S[0];
            S[1] *= egv; kv1 = kr[1] * S[1];
            S[2] *= egv; kv2 = kr[2] * S[2];
            S[3] *= egv; kv3 = kr[3] * S[3];
            S[4] *= egv; kv0 = fmaf(kr[4], S[4], kv0);
            S[5] *= egv; kv1 = fmaf(kr[5], S[5], kv1);
            S[6] *= egv; kv2 = fmaf(kr[6], S[6], kv2);
            S[7] *= egv; kv3 = fmaf(kr[7], S[7], kv3);
            float kv = (kv0 + kv1) + (kv2 + kv3);
            kv += __shfl_xor_sync(0xffffffffu, kv, 1);
            kv += __shfl_xor_sync(0xffffffffu, kv, 2);
            kv += __shfl_xor_sync(0xffffffffu, kv, 4);
            float vn = (vv - kv) * bt;
            float qv[8];
            *(float4*)&qv[0] = *(const float4*)&qs[set][s][qr*8];
            *(float4*)&qv[4] = *(const float4*)&qs[set][s][qr*8 + 4];
            float o0, o1, o2, o3;
            S[0] = fmaf(kr[0], vn, S[0]); o0 = qv[0] * S[0];
            S[1] = fmaf(kr[1], vn, S[1]); o1 = qv[1] * S[1];
            S[2] = fmaf(kr[2], vn, S[2]); o2 = qv[2] * S[2];
            S[3] = fmaf(kr[3], vn, S[3]); o3 = qv[3] * S[3];
            S[4] = fmaf(kr[4], vn, S[4]); o0 = fmaf(qv[4], S[4], o0);
            S[5] = fmaf(kr[5], vn, S[5]); o1 = fmaf(qv[5], S[5], o1);
            S[6] = fmaf(kr[6], vn, S[6]); o2 = fmaf(qv[6], S[6], o2);
            S[7] = fmaf(kr[7], vn, S[7]); o3 = fmaf(qv[7], S[7], o3);
            float oo = (o0 + o1) + (o2 + o3);
            oo += __shfl_xor_sync(0xffffffffu, oo, 1);
            oo += __shfl_xor_sync(0xffffffffu, oo, 2);
            oo += __shfl_xor_sync(0xffffffffu, oo, 4);
            if (qr == 0) o[((size_t)(p*4 + s) * H_ + h) * DV_ + dv] = oo;
        }
    }
    #undef ISSUE_STAGE
}

// ---------------- 5) gated RMSNorm + silu gate -> fp16 ----------------
__global__ void onorm_kernel(const float* __restrict__ o,
                             const float* __restrict__ gateb,
                             const float* __restrict__ onw,
                             __half* __restrict__ o2h) {
    int th = blockIdx.x;                 // t*H + h
    int t = th >> 4, h = th & 15;
    int i = threadIdx.x;                 // 0..127 = dv
    float val = o[(size_t)th * DV_ + i];
    float ss = val * val;
    for (int off = 16; off > 0; off >>= 1) ss += __shfl_xor_sync(0xffffffffu, ss, off);
    __shared__ float red[4];
    int warp = i >> 5, lane = i & 31;
    if (lane == 0) red[warp] = ss;
    __syncthreads();
    float tot = red[0] + red[1] + red[2] + red[3];
    float scale = rsqrtf(tot / (float)DV_ + 1e-5f);
    float gv = gateb[(size_t)t * BIGN_ + h * DV_ + i];
    float r = val * scale * onw[i] * (gv / (1.f + expf(-gv)));
    o2h[(size_t)th * DV_ + i] = __float2half_rn(r);
}

// ---------------- launcher ----------------
extern "C" void kernel_launch(void* const* d_in, const int* in_sizes, int n_in,
                              void* d_out, int out_size) {
    const float* hidden    = (const float*)d_in[0];
    const float* norm_w    = (const float*)d_in[1];
    const float* q_w       = (const float*)d_in[2];
    const float* k_w       = (const float*)d_in[3];
    const float* v_w       = (const float*)d_in[4];
    const float* a_w       = (const float*)d_in[5];
    const float* b_w       = (const float*)d_in[6];
    const float* g_w       = (const float*)d_in[7];
    const float* dt_bias   = (const float*)d_in[8];
    const float* A_log     = (const float*)d_in[9];
    const float* conv_q_w  = (const float*)d_in[10];
    const float* conv_k_w  = (const float*)d_in[11];
    const float* conv_v_w  = (const float*)d_in[12];
    const float* o_norm_w  = (const float*)d_in[13];
    const float* o_proj_w  = (const float*)d_in[14];
    const float* out_proj_w= (const float*)d_in[15];
    float* out = (float*)d_out;

    float *prs, *pbig, *pq, *pk, *pv, *pbeta, *peg, *po;
    __half *pwt, *pxh, *po2h, *py1h;
    cudaGetSymbolAddress((void**)&pwt,   g_wt);
    cudaGetSymbolAddress((void**)&pxh,   g_xh);
    cudaGetSymbolAddress((void**)&prs,   g_rs);
    cudaGetSymbolAddress((void**)&pbig,  g_big);
    cudaGetSymbolAddress((void**)&pq,    g_q);
    cudaGetSymbolAddress((void**)&pk,    g_k);
    cudaGetSymbolAddress((void**)&pv,    g_v);
    cudaGetSymbolAddress((void**)&pbeta, g_beta);
    cudaGetSymbolAddress((void**)&peg,   g_eg);
    cudaGetSymbolAddress((void**)&po,    g_o);
    cudaGetSymbolAddress((void**)&po2h,  g_o2h);
    cudaGetSymbolAddress((void**)&py1h,  g_y1h);

    cudaFuncSetAttribute(gemm128_h<0>, cudaFuncAttributeMaxDynamicSharedMemorySize, 61440);
    cudaFuncSetAttribute(gemm128_h<1>, cudaFuncAttributeMaxDynamicSharedMemorySize, 61440);

    // 1) weights -> fp16 (single launch)
    cvt_all_h<<<4672, 256>>>(
        (const float4*)q_w, (const float4*)k_w, (const float4*)v_w,
        (const float4*)g_w, (const float4*)o_proj_w, (const float4*)out_proj_w,
        a_w, b_w, pwt);

    // 2,3) RMSNorm
    rms_reduce_kernel<<<T_/8, 256>>>(hidden, prs);
    rms_apply_kernel<<<(T_*HID_/4)/256, 256>>>(hidden, prs, norm_w, pxh);

    // 4) fused q/k/v/g/ab projection (launch #4 -> ncu slot)
    gemm128_h<0><<<dim3(BIGN_/128, T_/128), 256, 61440>>>(pxh, pwt + WQKVG_OFF,
                                                          pbig, nullptr, HID_, BIGN_);

    // 5) conv(q,k)+norms+beta/eg ; 6) conv(v)
    conv_qk_kernel<<<(T_*H_*32)/256, 256>>>(pbig, conv_q_w, conv_k_w,
                                            dt_bias, A_log, pq, pk, pbeta, peg);
    conv_v_kernel<<<(T_*VAL_/4)/256, 256>>>(pbig, conv_v_w, pv);

    // 7) scan
    scan_kernel<<<H_*8, 128>>>(pq, pk, pv, pbeta, peg, po);

    // 8) gated output norm -> fp16
    onorm_kernel<<<T_*H_, 128>>>(po, pbig + 4096, o_norm_w, po2h);

    // 9,10) output projections (128-row tiles, reverted from R13)
    gemm128_h<1><<<dim3(HID_/128, T_/128), 256, 61440>>>(po2h, pwt + WO_OFF,
                                                         nullptr, py1h, VAL_, HID_);
    gemm128_h<0><<<dim3(HID_/128, T_/128), 256, 61440>>>(py1h, pwt + WOUT_OFF,
                                                         out, nullptr, HID_, HID_);
}

// round 16
// speedup vs baseline: 1.0165x; 1.0165x over previous
#include <cuda_runtime.h>
#include <cuda_fp16.h>
#include <math.h>

// ---------------- problem dims (fixed) ----------------
#define T_    2048
#define HID_  1024
#define H_    16
#define DK_   64
#define DV_   128
#define VAL_  2048
#define QKD_  1024
#define CONV_ 4
#define BIGN_ 6272   // q(1024)+k(1024)+v(2048)+g(2048)+ab_pad(128)
#define PLANE_ (T_*HID_)                // split-K partial plane (floats)

// fp16 weight buffer offsets (halves)
#define WQKVG_OFF 0u
#define WAB_OFF   6291456u              // 6144*1024
#define WO_OFF    6422528u              // + 128*1024
#define WOUT_OFF  8519680u              // + 1024*2048
#define WT_HALVES 9568256u              // + 1024*1024

// ---------------- scratch (device globals) ----------------
__device__ __half g_wt  [WT_HALVES];
__device__ __half g_xh  [T_*HID_];
__device__ float  g_rs  [T_];
__device__ float  g_big [T_*BIGN_];
__device__ float  g_q   [T_*QKD_];
__device__ float  g_k   [T_*QKD_];
__device__ float  g_v   [T_*VAL_];
__device__ float  g_beta[T_*H_];
__device__ float  g_eg  [T_*H_];
__device__ float  g_o   [T_*VAL_];
__device__ __half g_o2h [T_*VAL_];
__device__ __half g_y1h [T_*HID_];
__device__ float  g_part[2*PLANE_];     // split-K partials

// ---------------- helpers ----------------
__device__ __forceinline__ unsigned pack2(float a, float b) {
    __half2 h = __floats2half2_rn(a, b);
    return *reinterpret_cast<unsigned*>(&h);
}
#define MMA_F16(C, A, B)                                                      \
    asm volatile("mma.sync.aligned.m16n8k16.row.col.f32.f16.f16.f32 "         \
                 "{%0,%1,%2,%3}, {%4,%5,%6,%7}, {%8,%9}, {%0,%1,%2,%3};"      \
                 : "+f"((C)[0]), "+f"((C)[1]), "+f"((C)[2]), "+f"((C)[3])     \
                 : "r"((A)[0]), "r"((A)[1]), "r"((A)[2]), "r"((A)[3]),        \
                   "r"((B)[0]), "r"((B)[1]))
#define LDSM4(R0, R1, R2, R3, addr)                                           \
    asm volatile("ldmatrix.sync.aligned.m8n8.x4.shared.b16 {%0,%1,%2,%3}, [%4];" \
                 : "=r"(R0), "=r"(R1), "=r"(R2), "=r"(R3) : "r"(addr))
#define CP16(dst, src) \
    asm volatile("cp.async.cg.shared.global [%0], [%1], 16;\n" :: "r"(dst), "l"(src))

// ---------------- 0) ALL weights -> fp16 (single kernel) ----------------
__global__ void cvt_all_h(const float4* __restrict__ wq,
                          const float4* __restrict__ wk,
                          const float4* __restrict__ wv,
                          const float4* __restrict__ wg,
                          const float4* __restrict__ wo,
                          const float4* __restrict__ wout,
                          const float*  __restrict__ a_w,
                          const float*  __restrict__ b_w,
                          __half* __restrict__ dst) {
    int idx = blockIdx.x * 256 + threadIdx.x;       // 0 .. 1196031
    if (idx < 1179648) {
        int f4 = idx * 2;
        const float4* src; int off;
        if (f4 < 262144)       { src = wq;   off = f4; }
        else if (f4 < 524288)  { src = wk;   off = f4 - 262144; }
        else if (f4 < 1048576) { src = wv;   off = f4 - 524288; }
        else if (f4 < 1572864) { src = wg;   off = f4 - 1048576; }
        else if (f4 < 2097152) { src = wo;   off = f4 - 1572864; }
        else                   { src = wout; off = f4 - 2097152; }
        unsigned hbase = (unsigned)idx * 8;
        if (hbase >= WAB_OFF) hbase += 131072;      // skip ab region
        float4 v0 = src[off], v1 = src[off + 1];
        uint4 u;
        u.x = pack2(v0.x, v0.y); u.y = pack2(v0.z, v0.w);
        u.z = pack2(v1.x, v1.y); u.w = pack2(v1.z, v1.w);
        *(uint4*)&dst[hbase] = u;
    } else {
        int u2 = idx - 1179648;                     // 0..16383
        int base = u2 * 8;
        int row = base >> 10, col = base & 1023;
        float vals[8];
        #pragma unroll
        for (int i = 0; i < 8; i++) vals[i] = 0.f;
        if (row < 16) {
            #pragma unroll
            for (int i = 0; i < 8; i++) vals[i] = a_w[row * 1024 + col + i];
        } else if (row < 32) {
            #pragma unroll
            for (int i = 0; i < 8; i++) vals[i] = b_w[(row - 16) * 1024 + col + i];
        }
        uint4 uu;
        uu.x = pack2(vals[0], vals[1]); uu.y = pack2(vals[2], vals[3]);
        uu.z = pack2(vals[4], vals[5]); uu.w = pack2(vals[6], vals[7]);
        *(uint4*)&dst[WAB_OFF + base] = uu;
    }
}

// ---------------- 1a) RMSNorm reduce ----------------
__global__ void rms_reduce_kernel(const float* __restrict__ h,
                                  float* __restrict__ rs) {
    int row = blockIdx.x * 8 + (threadIdx.x >> 5);
    int lane = threadIdx.x & 31;
    const float4* p = (const float4*)(h + (size_t)row * HID_);
    float ss = 0.f;
    #pragma unroll
    for (int i = 0; i < 8; i++) {
        float4 v = p[lane + i * 32];
        ss += v.x * v.x + v.y * v.y + v.z * v.z + v.w * v.w;
    }
    for (int off = 16; off > 0; off >>= 1) ss += __shfl_xor_sync(0xffffffffu, ss, off);
    if (lane == 0) rs[row] = rsqrtf(ss / (float)HID_ + 1e-6f);
}

// ---------------- 1b) RMSNorm apply -> fp16 ----------------
__global__ void rms_apply_kernel(const float* __restrict__ h,
                                 const float* __restrict__ rs,
                                 const float* __restrict__ w,
                                 __half* __restrict__ xh) {
    int idx = blockIdx.x * blockDim.x + threadIdx.x;
    int t = idx >> 8;
    float s = rs[t];
    float4 hv = ((const float4*)h)[idx];
    float4 wv = ((const float4*)w)[idx & 255];
    uint2 u;
    u.x = pack2(hv.x * s * wv.x, hv.y * s * wv.y);
    u.y = pack2(hv.z * s * wv.z, hv.w * s * wv.w);
    ((uint2*)xh)[idx] = u;
}

// ---------------- 2) 128x128 FP16 GEMM, 3-stage cp.async + ldmatrix -------
// blockIdx.z selects a K-slice of length Kpart (split-K); output goes to
// Cf + blockIdx.z * plane (float partials; plane=0, gridDim.z=1 -> plain GEMM)
#define HPAD 40
#define STAGEB 10240u                   // 128*40 halves * 2B
__global__ __launch_bounds__(256, 2) void gemm128_h(const __half* __restrict__ X,
                                                    const __half* __restrict__ W,
                                                    float* __restrict__ Cf,
                                                    int Kfull, int Kpart,
                                                    int ldc, size_t plane) {
    extern __shared__ __half smem[];    // [A0 A1 A2 B0 B1 B2], 10240B each
    int z = blockIdx.z;
    const __half* Xt = X + (size_t)blockIdx.y * 128 * Kfull + (size_t)z * Kpart;
    const __half* Wt = W + (size_t)blockIdx.x * 128 * Kfull + (size_t)z * Kpart;
    int tid = threadIdx.x, wid = tid >> 5, lane = tid & 31;
    int wm = (wid >> 2) * 64, wn = (wid & 3) * 32;
    int gid = lane >> 2, tig = lane & 3;
    int t4 = lane >> 3, l8 = lane & 7;
    int aRow = (t4 & 1) * 8 + l8, aCol = (t4 >> 1) * 8;
    int bRow = (t4 >> 1) * 8 + l8, bCol = (t4 & 1) * 8;

    int lr = tid >> 1, hc = (tid & 1) * 16;
    const __half* xs = Xt + (size_t)lr * Kfull + hc;
    const __half* ws = Wt + (size_t)lr * Kfull + hc;
    unsigned abase = (unsigned)__cvta_generic_to_shared(smem);
    unsigned bbase = abase + 3 * STAGEB;
    unsigned woff = (unsigned)(lr * HPAD + hc) * 2;

    float acc[16][4];
    #pragma unroll
    for (int i = 0; i < 16; i++)
        #pragma unroll
        for (int j = 0; j < 4; j++) acc[i][j] = 0.f;

    // prologue: stages 0,1
    #pragma unroll
    for (int s = 0; s < 2; s++) {
        unsigned da = abase + s * STAGEB + woff;
        unsigned db = bbase + s * STAGEB + woff;
        int k0 = s * 32;
        CP16(da, xs + k0); CP16(da + 16, xs + k0 + 8);
        CP16(db, ws + k0); CP16(db + 16, ws + k0 + 8);
        asm volatile("cp.async.commit_group;\n");
    }

    int nk = Kpart / 32;
    for (int it = 0; it < nk; it++) {
        asm volatile("cp.async.wait_group 1;\n");   // stage `it` ready
        __syncthreads();
        if (it + 2 < nk) {
            int s = (it + 2) % 3;
            int k0 = (it + 2) * 32;
            unsigned da = abase + s * STAGEB + woff;
            unsigned db = bbase + s * STAGEB + woff;
            CP16(da, xs + k0); CP16(da + 16, xs + k0 + 8);
            CP16(db, ws + k0); CP16(db + 16, ws + k0 + 8);
        }
        asm volatile("cp.async.commit_group;\n");
        unsigned ab = abase + (it % 3) * STAGEB;
        unsigned bb = bbase + (it % 3) * STAGEB;
        #pragma unroll
        for (int k16 = 0; k16 < 2; k16++) {
            int kk = k16 * 16;
            unsigned a[4][4], b[4][2];
            #pragma unroll
            for (int mt = 0; mt < 4; mt++) {
                unsigned addr = ab + ((wm + mt * 16 + aRow) * HPAD + kk + aCol) * 2;
                LDSM4(a[mt][0], a[mt][1], a[mt][2], a[mt][3], addr);
            }
            #pragma unroll
            for (int p = 0; p < 2; p++) {
                unsigned addr = bb + ((wn + p * 16 + bRow) * HPAD + kk + bCol) * 2;
                LDSM4(b[p*2][0], b[p*2][1], b[p*2+1][0], b[p*2+1][1], addr);
            }
            #pragma unroll
            for (int mt = 0; mt < 4; mt++)
                #pragma unroll
                for (int nt = 0; nt < 4; nt++)
                    MMA_F16(acc[mt * 4 + nt], a[mt], b[nt]);
        }
    }

    size_t base = (size_t)z * plane + (size_t)blockIdx.y * 128 * ldc + blockIdx.x * 128;
    #pragma unroll
    for (int mt = 0; mt < 4; mt++) {
        int row = wm + mt * 16 + gid;
        #pragma unroll
        for (int nt = 0; nt < 4; nt++) {
            int col = wn + nt * 8 + tig * 2;
            float* c = acc[mt * 4 + nt];
            *(float2*)&Cf[base + (size_t)row * ldc + col]       = make_float2(c[0], c[1]);
            *(float2*)&Cf[base + (size_t)(row + 8) * ldc + col] = make_float2(c[2], c[3]);
        }
    }
}

// ---------------- 2b) split-K combine ----------------
__global__ void combine_h_kernel(const float* __restrict__ p,
                                 __half* __restrict__ outh) {
    int idx = blockIdx.x * 256 + threadIdx.x;      // float4 units
    float4 a = ((const float4*)p)[idx];
    float4 b = ((const float4*)(p + PLANE_))[idx];
    uint2 u;
    u.x = pack2(a.x + b.x, a.y + b.y);
    u.y = pack2(a.z + b.z, a.w + b.w);
    ((uint2*)outh)[idx] = u;
}
__global__ void combine_f_kernel(const float* __restrict__ p,
                                 float* __restrict__ outf) {
    int idx = blockIdx.x * 256 + threadIdx.x;      // float4 units
    float4 a = ((const float4*)p)[idx];
    float4 b = ((const float4*)(p + PLANE_))[idx];
    float4 r = make_float4(a.x + b.x, a.y + b.y, a.z + b.z, a.w + b.w);
    ((float4*)outf)[idx] = r;
}

// ---------------- 3a) conv(q,k) + silu + DC-removal + L2 norm + beta/eg ---
__global__ void conv_qk_kernel(const float* __restrict__ big,
                               const float* __restrict__ wq,
                               const float* __restrict__ wk,
                               const float* __restrict__ dt_bias,
                               const float* __restrict__ A_log,
                               float* __restrict__ qout,
                               float* __restrict__ kout,
                               float* __restrict__ beta,
                               float* __restrict__ eg) {
    int gw = (blockIdx.x * blockDim.x + threadIdx.x) >> 5;  // t*H + h
    int lane = threadIdx.x & 31;
    int t = gw >> 4, h = gw & 15;
    float da = 0.f, db = 0.f;
    if (lane == 0) {
        da = big[(size_t)t * BIGN_ + 6144 + h];
        db = big[(size_t)t * BIGN_ + 6160 + h];
    }
    int c0 = h * 64 + lane * 2;
    float4 wq0 = ((const float4*)wq)[c0], wq1 = ((const float4*)wq)[c0 + 1];
    float4 wk0 = ((const float4*)wk)[c0], wk1 = ((const float4*)wk)[c0 + 1];
    float q0 = 0.f, q1 = 0.f, k0 = 0.f, k1 = 0.f;
    #pragma unroll
    for (int i = 0; i < CONV_; i++) {
        int tt = t - 3 + i;
        if (tt >= 0) {
            const float* row = big + (size_t)tt * BIGN_;
            float2 xq = *(const float2*)(row + c0);
            float2 xk = *(const float2*)(row + 1024 + c0);
            q0 = fmaf(xq.x, (&wq0.x)[i], q0);
            q1 = fmaf(xq.y, (&wq1.x)[i], q1);
            k0 = fmaf(xk.x, (&wk0.x)[i], k0);
            k1 = fmaf(xk.y, (&wk1.x)[i], k1);
        }
    }
    q0 *= 1.f / (1.f + __expf(-q0));
    q1 *= 1.f / (1.f + __expf(-q1));
    k0 *= 1.f / (1.f + __expf(-k0));
    k1 *= 1.f / (1.f + __expf(-k1));
    float s = k0 + k1;
    for (int off = 16; off > 0; off >>= 1) s += __shfl_xor_sync(0xffffffffu, s, off);
    float mean = s * (1.f / 64.f);
    k0 -= mean; k1 -= mean;
    float ss = k0 * k0 + k1 * k1;
    for (int off = 16; off > 0; off >>= 1) ss += __shfl_xor_sync(0xffffffffu, ss, off);
    float sc = rsqrtf(ss + 1e-6f);
    float qq = q0 * q0 + q1 * q1;
    for (int off = 16; off > 0; off >>= 1) qq += __shfl_xor_sync(0xffffffffu, qq, off);
    float qs = rsqrtf(qq + 1e-6f) * 0.125f;
    *(float2*)&qout[(size_t)gw * DK_ + lane * 2] = make_float2(q0 * qs, q1 * qs);
    *(float2*)&kout[(size_t)gw * DK_ + lane * 2] = make_float2(k0 * sc, k1 * sc);
    if (lane == 0) {
        beta[gw] = 1.f / (1.f + expf(-db));
        float z = da + dt_bias[h];
        float sp = (z > 20.f) ? z : log1pf(expf(z));
        eg[gw] = expf(-expf(A_log[h]) * sp);
    }
}

// ---------------- 3b) conv(v) + silu ----------------
__global__ void conv_v_kernel(const float* __restrict__ big,
                              const float* __restrict__ wv,
                              float* __restrict__ ov) {
    int idx = blockIdx.x * 256 + threadIdx.x;   // over T_*2048/4
    int t = idx >> 9;
    int c4 = (idx & 511) * 4;
    float4 w0 = ((const float4*)wv)[c4 + 0];
    float4 w1 = ((const float4*)wv)[c4 + 1];
    float4 w2 = ((const float4*)wv)[c4 + 2];
    float4 w3 = ((const float4*)wv)[c4 + 3];
    float4 acc = make_float4(0.f, 0.f, 0.f, 0.f);
    #pragma unroll
    for (int i = 0; i < CONV_; i++) {
        int tt = t - 3 + i;
        if (tt >= 0) {
            float4 xv = *(const float4*)(big + (size_t)tt * BIGN_ + 2048 + c4);
            acc.x = fmaf(xv.x, (&w0.x)[i], acc.x);
            acc.y = fmaf(xv.y, (&w1.x)[i], acc.y);
            acc.z = fmaf(xv.z, (&w2.x)[i], acc.z);
            acc.w = fmaf(xv.w, (&w3.x)[i], acc.w);
        }
    }
    acc.x *= 1.f / (1.f + __expf(-acc.x));
    acc.y *= 1.f / (1.f + __expf(-acc.y));
    acc.z *= 1.f / (1.f + __expf(-acc.z));
    acc.w *= 1.f / (1.f + __expf(-acc.w));
    *(float4*)&ov[(size_t)t * VAL_ + c4] = acc;
}

// ---------------- 4) gated delta-rule scan (dv split 8) ----------------
__global__ __launch_bounds__(128) void scan_kernel(const float* __restrict__ q,
                                                   const float* __restrict__ k,
                                                   const float* __restrict__ v,
                                                   const float* __restrict__ beta,
                                                   const float* __restrict__ eg,
                                                   float* __restrict__ o) {
    int h = blockIdx.x >> 3;
    int dvq = blockIdx.x & 7;
    int tid = threadIdx.x;
    int dv_l = tid >> 3, qr = tid & 7;
    int dv = dvq * 16 + dv_l;

    __shared__ float ks[4][4][64], qs[4][4][64], vs[4][4][16], gb[4][4][2];

    int role = tid >> 5;
    int lane = tid & 31;

    float S[8];
    #pragma unroll
    for (int i = 0; i < 8; i++) S[i] = 0.f;

    const int NP = T_ / 4;   // 512 stages

    #define ISSUE_STAGE(P) do {                                                       \
        int set_ = (P) & 3;                                                           \
        int t0_ = (P) * 4;                                                            \
        if (role == 0) {                                                              \
            _Pragma("unroll")                                                         \
            for (int r2 = 0; r2 < 2; r2++) {                                          \
                int idx = lane + r2 * 32;                                             \
                int ss = idx >> 4, ch = idx & 15;                                     \
                unsigned d = (unsigned)__cvta_generic_to_shared(&ks[set_][ss][ch*4]); \
                const float* sp = k + ((size_t)(t0_ + ss) * H_ + h) * DK_ + ch*4;     \
                CP16(d, sp);                                                          \
            }                                                                         \
        } else if (role == 1) {                                                       \
            _Pragma("unroll")                                                         \
            for (int r2 = 0; r2 < 2; r2++) {                                          \
                int idx = lane + r2 * 32;                                             \
                int ss = idx >> 4, ch = idx & 15;                                     \
                unsigned d = (unsigned)__cvta_generic_to_shared(&qs[set_][ss][ch*4]); \
                const float* sp = q + ((size_t)(t0_ + ss) * H_ + h) * DK_ + ch*4;     \
                CP16(d, sp);                                                          \
            }                                                                         \
        } else if (role == 2) {                                                       \
            if (lane < 16) {                                                          \
                int ss = lane >> 2, ch = lane & 3;                                    \
                unsigned d = (unsigned)__cvta_generic_to_shared(&vs[set_][ss][ch*4]); \
                const float* sp = v + ((size_t)(t0_ + ss) * H_ + h) * DV_ + dvq*16 + ch*4; \
                CP16(d, sp);                                                          \
            }                                                                         \
        } else if (lane < 8) {                                                        \
            int ss = lane >> 1; int which = lane & 1;                                 \
            unsigned d = (unsigned)__cvta_generic_to_shared(&gb[set_][ss][which]);    \
            const float* sp = (which ? beta : eg) + (size_t)(t0_ + ss) * H_ + h;      \
            asm volatile("cp.async.ca.shared.global [%0], [%1], 4;\n" :: "r"(d), "l"(sp)); \
        }                                                                             \
    } while (0)

    #pragma unroll
    for (int p = 0; p < 3; p++) {
        ISSUE_STAGE(p);
        asm volatile("cp.async.commit_group;\n");
    }

    for (int p = 0; p < NP; p++) {
        asm volatile("cp.async.wait_group 2;\n");
        __syncthreads();
        if (p + 3 < NP) ISSUE_STAGE(p + 3);
        asm volatile("cp.async.commit_group;\n");
        int set = p & 3;
        #pragma unroll
        for (int s = 0; s < 4; s++) {
            float egv = gb[set][s][0];
            float bt  = gb[set][s][1];
            float vv  = vs[set][s][dv_l];
            float kr[8];
            *(float4*)&kr[0] = *(const float4*)&ks[set][s][qr*8];
            *(float4*)&kr[4] = *(const float4*)&ks[set][s][qr*8 + 4];
            float kv0, kv1, kv2, kv3;
            S[0] *= egv; kv0 = kr[0] * S[0];
            S[1] *= egv; kv1 = kr[1] * S[1];
            S[2] *= egv; kv2 = kr[2] * S[2];
            S[3] *= egv; kv3 = kr[3] * S[3];
            S[4] *= egv; kv0 = fmaf(kr[4], S[4], kv0);
            S[5] *= egv; kv1 = fmaf(kr[5], S[5], kv1);
            S[6] *= egv; kv2 = fmaf(kr[6], S[6], kv2);
            S[7] *= egv; kv3 = fmaf(kr[7], S[7], kv3);
            float kv = (kv0 + kv1) + (kv2 + kv3);
            kv += __shfl_xor_sync(0xffffffffu, kv, 1);
            kv += __shfl_xor_sync(0xffffffffu, kv, 2);
            kv += __shfl_xor_sync(0xffffffffu, kv, 4);
            float vn = (vv - kv) * bt;
            float qv[8];
            *(float4*)&qv[0] = *(const float4*)&qs[set][s][qr*8];
            *(float4*)&qv[4] = *(const float4*)&qs[set][s][qr*8 + 4];
            float o0, o1, o2, o3;
            S[0] = fmaf(kr[0], vn, S[0]); o0 = qv[0] * S[0];
            S[1] = fmaf(kr[1], vn, S[1]); o1 = qv[1] * S[1];
            S[2] = fmaf(kr[2], vn, S[2]); o2 = qv[2] * S[2];
            S[3] = fmaf(kr[3], vn, S[3]); o3 = qv[3] * S[3];
            S[4] = fmaf(kr[4], vn, S[4]); o0 = fmaf(qv[4], S[4], o0);
            S[5] = fmaf(kr[5], vn, S[5]); o1 = fmaf(qv[5], S[5], o1);
            S[6] = fmaf(kr[6], vn, S[6]); o2 = fmaf(qv[6], S[6], o2);
            S[7] = fmaf(kr[7], vn, S[7]); o3 = fmaf(qv[7], S[7], o3);
            float oo = (o0 + o1) + (o2 + o3);
            oo += __shfl_xor_sync(0xffffffffu, oo, 1);
            oo += __shfl_xor_sync(0xffffffffu, oo, 2);
            oo += __shfl_xor_sync(0xffffffffu, oo, 4);
            if (qr == 0) o[((size_t)(p*4 + s) * H_ + h) * DV_ + dv] = oo;
        }
    }
    #undef ISSUE_STAGE
}

// ---------------- 5) gated RMSNorm + silu gate -> fp16 ----------------
__global__ void onorm_kernel(const float* __restrict__ o,
                             const float* __restrict__ gateb,
                             const float* __restrict__ onw,
                             __half* __restrict__ o2h) {
    int th = blockIdx.x;                 // t*H + h
    int t = th >> 4, h = th & 15;
    int i = threadIdx.x;                 // 0..127 = dv
    float val = o[(size_t)th * DV_ + i];
    float ss = val * val;
    for (int off = 16; off > 0; off >>= 1) ss += __shfl_xor_sync(0xffffffffu, ss, off);
    __shared__ float red[4];
    int warp = i >> 5, lane = i & 31;
    if (lane == 0) red[warp] = ss;
    __syncthreads();
    float tot = red[0] + red[1] + red[2] + red[3];
    float scale = rsqrtf(tot / (float)DV_ + 1e-5f);
    float gv = gateb[(size_t)t * BIGN_ + h * DV_ + i];
    float r = val * scale * onw[i] * (gv / (1.f + expf(-gv)));
    o2h[(size_t)th * DV_ + i] = __float2half_rn(r);
}

// ---------------- launcher ----------------
extern "C" void kernel_launch(void* const* d_in, const int* in_sizes, int n_in,
                              void* d_out, int out_size) {
    const float* hidden    = (const float*)d_in[0];
    const float* norm_w    = (const float*)d_in[1];
    const float* q_w       = (const float*)d_in[2];
    const float* k_w       = (const float*)d_in[3];
    const float* v_w       = (const float*)d_in[4];
    const float* a_w       = (const float*)d_in[5];
    const float* b_w       = (const float*)d_in[6];
    const float* g_w       = (const float*)d_in[7];
    const float* dt_bias   = (const float*)d_in[8];
    const float* A_log     = (const float*)d_in[9];
    const float* conv_q_w  = (const float*)d_in[10];
    const float* conv_k_w  = (const float*)d_in[11];
    const float* conv_v_w  = (const float*)d_in[12];
    const float* o_norm_w  = (const float*)d_in[13];
    const float* o_proj_w  = (const float*)d_in[14];
    const float* out_proj_w= (const float*)d_in[15];
    float* out = (float*)d_out;

    float *prs, *pbig, *pq, *pk, *pv, *pbeta, *peg, *po, *ppart;
    __half *pwt, *pxh, *po2h, *py1h;
    cudaGetSymbolAddress((void**)&pwt,   g_wt);
    cudaGetSymbolAddress((void**)&pxh,   g_xh);
    cudaGetSymbolAddress((void**)&prs,   g_rs);
    cudaGetSymbolAddress((void**)&pbig,  g_big);
    cudaGetSymbolAddress((void**)&pq,    g_q);
    cudaGetSymbolAddress((void**)&pk,    g_k);
    cudaGetSymbolAddress((void**)&pv,    g_v);
    cudaGetSymbolAddress((void**)&pbeta, g_beta);
    cudaGetSymbolAddress((void**)&peg,   g_eg);
    cudaGetSymbolAddress((void**)&po,    g_o);
    cudaGetSymbolAddress((void**)&po2h,  g_o2h);
    cudaGetSymbolAddress((void**)&py1h,  g_y1h);
    cudaGetSymbolAddress((void**)&ppart, g_part);

    cudaFuncSetAttribute(gemm128_h, cudaFuncAttributeMaxDynamicSharedMemorySize, 61440);

    // 1) weights -> fp16 (single launch)
    cvt_all_h<<<4672, 256>>>(
        (const float4*)q_w, (const float4*)k_w, (const float4*)v_w,
        (const float4*)g_w, (const float4*)o_proj_w, (const float4*)out_proj_w,
        a_w, b_w, pwt);

    // 2,3) RMSNorm
    rms_reduce_kernel<<<T_/8, 256>>>(hidden, prs);
    rms_apply_kernel<<<(T_*HID_/4)/256, 256>>>(hidden, prs, norm_w, pxh);

    // 4) fused q/k/v/g/ab projection (no split; launch #4 -> ncu slot)
    gemm128_h<<<dim3(BIGN_/128, T_/128, 1), 256, 61440>>>(
        pxh, pwt + WQKVG_OFF, pbig, HID_, HID_, BIGN_, 0);

    // 5) conv(q,k)+norms+beta/eg ; 6) conv(v)
    conv_qk_kernel<<<(T_*H_*32)/256, 256>>>(pbig, conv_q_w, conv_k_w,
                                            dt_bias, A_log, pq, pk, pbeta, peg);
    conv_v_kernel<<<(T_*VAL_/4)/256, 256>>>(pbig, conv_v_w, pv);

    // 7) scan
    scan_kernel<<<H_*8, 128>>>(pq, pk, pv, pbeta, peg, po);

    // 8) gated output norm -> fp16
    onorm_kernel<<<T_*H_, 128>>>(po, pbig + 4096, o_norm_w, po2h);

    // 9) o_proj: split-K=2 (256 CTAs) -> float partials -> fp16 combine
    gemm128_h<<<dim3(HID_/128, T_/128, 2), 256, 61440>>>(
        po2h, pwt + WO_OFF, ppart, VAL_, VAL_/2, HID_, PLANE_);
    combine_h_kernel<<<(PLANE_/4)/256, 256>>>(ppart, py1h);

    // 10) out_proj: split-K=2 -> float partials -> float combine into d_out
    gemm128_h<<<dim3(HID_/128, T_/128, 2), 256, 61440>>>(
        py1h, pwt + WOUT_OFF, ppart, HID_, HID_/2, HID_, PLANE_);
    combine_f_kernel<<<(PLANE_/4)/256, 256>>>(ppart, out);
}